// round 8
// baseline (speedup 1.0000x reference)
#include <cuda_runtime.h>
#include <cuda_bf16.h>
#include <math.h>

// Problem constants
#define BB   256
#define SS   256
#define DD   1024
#define PP   512
#define SH   254          // head rows = S - 2
#define MTILE 32
#define NTILES 8          // ceil(254/32)
#define THREADS_MAIN 128

// Scratch (static device globals; no runtime allocation)
__device__ float g_bias[BB * PP];     // per-batch (prep+child) projection bias
__device__ float g_mexp[BB * SH];     // masked exp scores
__device__ float g_sums[BB];          // per-batch exp sums

// ---- packed fp32x2 helpers (Blackwell FFMA2 path; ptxas only emits via PTX) ----
__device__ __forceinline__ unsigned long long pack2(float lo, float hi) {
    unsigned long long u;
    asm("mov.b64 %0, {%1, %2};" : "=l"(u) : "f"(lo), "f"(hi));
    return u;
}
__device__ __forceinline__ void unpack2(unsigned long long u, float& lo, float& hi) {
    asm("mov.b64 {%0, %1}, %2;" : "=f"(lo), "=f"(hi) : "l"(u));
}
__device__ __forceinline__ void ffma2(unsigned long long& d,
                                      unsigned long long a,
                                      unsigned long long b) {
    asm("fma.rn.f32x2 %0, %1, %2, %0;" : "+l"(d) : "l"(a), "l"(b));
}

// ---------------------------------------------------------------------------
// Kernel 1: bias[b][c] = x[b,254,:]@proj_prep[:,c] + x[b,255,:]@proj_child[:,c]
// Also zeroes g_sums[b] each replay.
// ---------------------------------------------------------------------------
__global__ void __launch_bounds__(512) bias_kernel(
    const float* __restrict__ x,
    const float* __restrict__ pp,
    const float* __restrict__ pc)
{
    __shared__ float rows[2 * DD];
    const int b = blockIdx.x;
    const int tid = threadIdx.x;

    const float* xprep  = x + ((size_t)b * SS + (SS - 2)) * DD;
    const float* xchild = x + ((size_t)b * SS + (SS - 1)) * DD;
    for (int i = tid; i < DD; i += 512) {
        rows[i]      = xprep[i];
        rows[DD + i] = xchild[i];
    }
    if (tid == 0) g_sums[b] = 0.0f;
    __syncthreads();

    const int c = tid;  // 512 threads = 512 columns
    float acc = 0.0f;
    #pragma unroll 4
    for (int k = 0; k < DD; k++)
        acc += rows[k] * pp[(size_t)k * PP + c];
    #pragma unroll 4
    for (int k = 0; k < DD; k++)
        acc += rows[DD + k] * pc[(size_t)k * PP + c];
    g_bias[b * PP + c] = acc;
}

// ---------------------------------------------------------------------------
// Kernel 2: fused head projection + 2 hidden layers + scorer + masked exp.
// Grid: (NTILES, BB). Block: 128 threads, each owns 4 contiguous columns,
// kept as 2 packed fp32x2 accumulators per row (FFMA2 path).
// smem: Xs chunk 32x128 (16KB) + Cs composed tile 32x512 (64KB) = 80KB.
// ---------------------------------------------------------------------------
extern __shared__ float sm_main[];

__global__ void __launch_bounds__(THREADS_MAIN) main_kernel(
    const float* __restrict__ x,
    const float* __restrict__ Wh,       // proj_head (1024,512)
    const float* __restrict__ Wl,       // hidden_layers (2,512,512)
    const float* __restrict__ scorer,   // (512,)
    const unsigned int* __restrict__ maskp) // (256,256) int32/float32 bool
{
    float* Xs = sm_main;                // 32*128 floats
    float* Cs = sm_main + MTILE * 128;  // 32*512 floats

    const int tile = blockIdx.x;
    const int b    = blockIdx.y;
    const int s0   = tile * MTILE;
    const int nrows = min(MTILE, SH - s0);
    const int tid  = threadIdx.x;
    const int c0   = tid * 4;

    unsigned long long acc01[MTILE], acc23[MTILE];
    #pragma unroll
    for (int r = 0; r < MTILE; r++) { acc01[r] = 0ull; acc23[r] = 0ull; }

    const float* xb = x + (size_t)b * SS * DD;

    // ---- Phase 1: head projection (K = 1024, streamed in 128-chunks) ----
    for (int k0 = 0; k0 < DD; k0 += 128) {
        // load Xs[32][128] (rows beyond 253 are in-bounds garbage; masked later)
        for (int i = tid; i < MTILE * 32; i += THREADS_MAIN) {
            int r = i >> 5, kk = i & 31;
            ((float4*)Xs)[i] =
                ((const float4*)(xb + (size_t)(s0 + r) * DD + k0))[kk];
        }
        __syncthreads();

        #pragma unroll 2
        for (int k = 0; k < 128; k++) {
            float4 w = *(const float4*)(Wh + (size_t)(k0 + k) * PP + c0);
            unsigned long long w01 = pack2(w.x, w.y);
            unsigned long long w23 = pack2(w.z, w.w);
            #pragma unroll
            for (int r = 0; r < MTILE; r++) {
                float a = Xs[r * 128 + k];
                unsigned long long aa = pack2(a, a);
                ffma2(acc01[r], aa, w01);
                ffma2(acc23[r], aa, w23);
            }
        }
        __syncthreads();
    }

    // ---- bias + tanh -> Cs ----
    {
        float4 bb = *(const float4*)(g_bias + b * PP + c0);
        #pragma unroll
        for (int r = 0; r < MTILE; r++) {
            float ax, ay, az, aw;
            unpack2(acc01[r], ax, ay);
            unpack2(acc23[r], az, aw);
            float4 v;
            v.x = tanhf(ax + bb.x);
            v.y = tanhf(ay + bb.y);
            v.z = tanhf(az + bb.z);
            v.w = tanhf(aw + bb.w);
            *(float4*)(Cs + r * PP + c0) = v;
        }
    }
    __syncthreads();

    // ---- Hidden layers (x2): acc = Cs @ W; tanh; L0 writes back to Cs ----
    float4 last[MTILE];   // tanh outputs of the final layer, for scorer
    for (int L = 0; L < 2; L++) {
        const float* W = Wl + (size_t)L * PP * PP;
        #pragma unroll
        for (int r = 0; r < MTILE; r++) { acc01[r] = 0ull; acc23[r] = 0ull; }

        #pragma unroll 2
        for (int k = 0; k < PP; k++) {
            float4 w = *(const float4*)(W + (size_t)k * PP + c0);
            unsigned long long w01 = pack2(w.x, w.y);
            unsigned long long w23 = pack2(w.z, w.w);
            #pragma unroll
            for (int r = 0; r < MTILE; r++) {
                float a = Cs[r * PP + k];
                unsigned long long aa = pack2(a, a);
                ffma2(acc01[r], aa, w01);
                ffma2(acc23[r], aa, w23);
            }
        }
        __syncthreads();   // all reads of Cs done before overwrite

        #pragma unroll
        for (int r = 0; r < MTILE; r++) {
            float ax, ay, az, aw;
            unpack2(acc01[r], ax, ay);
            unpack2(acc23[r], az, aw);
            float4 v;
            v.x = tanhf(ax);
            v.y = tanhf(ay);
            v.z = tanhf(az);
            v.w = tanhf(aw);
            if (L == 0) *(float4*)(Cs + r * PP + c0) = v;
            else        last[r] = v;
        }
        if (L == 0) __syncthreads();
    }

    // ---- scorer dot: p[r] = sum_c composed2[r][c] * scorer[c] ----
    float4 sc = *(const float4*)(scorer + c0);
    const int lane = tid & 31, warp = tid >> 5;
    float myscore = 0.0f;
    #pragma unroll
    for (int r = 0; r < MTILE; r++) {
        float v = last[r].x * sc.x + last[r].y * sc.y
                + last[r].z * sc.z + last[r].w * sc.w;
        v += __shfl_xor_sync(0xffffffffu, v, 16);
        v += __shfl_xor_sync(0xffffffffu, v, 8);
        v += __shfl_xor_sync(0xffffffffu, v, 4);
        v += __shfl_xor_sync(0xffffffffu, v, 2);
        v += __shfl_xor_sync(0xffffffffu, v, 1);
        if (lane == r) myscore = v;   // lane r holds row r's partial (this warp)
    }

    float* red = Xs;                  // reuse Xs region (phase 1 is long done)
    __syncthreads();
    red[warp * 32 + lane] = myscore;
    __syncthreads();

    if (warp == 0) {
        float total = red[lane] + red[32 + lane] + red[64 + lane] + red[96 + lane];
        const int s = s0 + lane;
        float e = 0.0f;
        if (lane < nrows) {
            // mask arrives as int32 (or float32) "bool": 32-bit word nonzero <=> true
            unsigned int m = maskp[b * SS + s];
            if (m != 0u) e = expf(total);
            g_mexp[b * SH + s] = e;
        }
        float t = e;
        t += __shfl_xor_sync(0xffffffffu, t, 16);
        t += __shfl_xor_sync(0xffffffffu, t, 8);
        t += __shfl_xor_sync(0xffffffffu, t, 4);
        t += __shfl_xor_sync(0xffffffffu, t, 2);
        t += __shfl_xor_sync(0xffffffffu, t, 1);
        if (lane == 0) atomicAdd(&g_sums[b], t);
    }
}

// ---------------------------------------------------------------------------
// Kernel 3: out[b][s] = g_mexp[b][s] / (g_sums[b] + 1e-7)
// ---------------------------------------------------------------------------
__global__ void norm_kernel(float* __restrict__ out)
{
    int i = blockIdx.x * blockDim.x + threadIdx.x;
    if (i < BB * SH) {
        int b = i / SH;
        out[i] = g_mexp[i] / (g_sums[b] + 1e-7f);
    }
}

// ---------------------------------------------------------------------------
extern "C" void kernel_launch(void* const* d_in, const int* in_sizes, int n_in,
                              void* d_out, int out_size)
{
    const float* x       = (const float*)d_in[0];
    const float* ph      = (const float*)d_in[1];
    const float* pp      = (const float*)d_in[2];
    const float* pc      = (const float*)d_in[3];
    const float* hidden  = (const float*)d_in[4];
    const float* scorer  = (const float*)d_in[5];
    const unsigned int* mask = (const unsigned int*)d_in[6];
    float* out = (float*)d_out;

    const int smem_bytes = (MTILE * 128 + MTILE * PP) * (int)sizeof(float); // 80KB
    cudaFuncSetAttribute(main_kernel,
                         cudaFuncAttributeMaxDynamicSharedMemorySize, smem_bytes);

    bias_kernel<<<BB, 512>>>(x, pp, pc);

    dim3 grid(NTILES, BB);
    main_kernel<<<grid, THREADS_MAIN, smem_bytes>>>(x, ph, hidden, scorer, mask);

    norm_kernel<<<(BB * SH + 255) / 256, 256>>>(out);
}

// round 12
// speedup vs baseline: 3.9705x; 3.9705x over previous
#include <cuda_runtime.h>
#include <math.h>
#include <stdint.h>

// ---------------- problem constants ----------------
#define BB 256
#define DD 1024
#define PP 512
#define SH 254

// ---------------- device scratch (static; no runtime alloc) ----------------
__device__ float g_xr[67108864];     // x, tf32-rounded (256MB)
__device__ float g_wt[1048576];      // Wh | W1 | W2, [K][N], tf32-rounded
__device__ float g_cA[33554432];     // layer staging A (134MB)
__device__ float g_cB[33554432];     // layer staging B (134MB)
__device__ float g_bias[BB * PP];    // prep+child projection bias
__device__ float g_score[65536];     // raw scores (b*256 + s)

// ---------------- helpers ----------------
__device__ __forceinline__ uint32_t smem_u32(const void* p) {
    uint32_t a;
    asm("{ .reg .u64 t; cvta.to.shared.u64 t, %1; cvt.u32.u64 %0, t; }"
        : "=r"(a) : "l"(p));
    return a;
}
__device__ __forceinline__ float tf32r(float x) {   // round-to-nearest tf32
    uint32_t u;
    asm("cvt.rna.tf32.f32 %0, %1;" : "=r"(u) : "f"(x));
    return __uint_as_float(u);
}
__device__ __forceinline__ float tanh_fast(float x) {
    float y;
    asm("tanh.approx.f32 %0, %1;" : "=f"(y) : "f"(x));
    return y;
}
__device__ __forceinline__ void cpa16(uint32_t d, const void* s) {
    asm volatile("cp.async.cg.shared.global [%0], [%1], 16;" :: "r"(d), "l"(s));
}

// ---------------------------------------------------------------------------
// init: zero g_bias + g_score each replay
// ---------------------------------------------------------------------------
__global__ void init_kernel() {
    int i = blockIdx.x * blockDim.x + threadIdx.x;
    if (i < BB * PP) g_bias[i] = 0.0f;
    if (i < 65536)   g_score[i] = 0.0f;
}

// ---------------------------------------------------------------------------
// round weights into g_wt ([K][N] layout preserved), tf32 rna
// ---------------------------------------------------------------------------
__global__ void round_w_kernel(const float* __restrict__ ph,
                               const float* __restrict__ hidden) {
    int i = blockIdx.x * blockDim.x + threadIdx.x;
    for (; i < 1048576; i += gridDim.x * blockDim.x)
        g_wt[i] = tf32r(i < 524288 ? ph[i] : hidden[i - 524288]);
}

// ---------------------------------------------------------------------------
// round x into g_xr, tf32 rna (float4 grid-stride)
// ---------------------------------------------------------------------------
__global__ void round_x_kernel(const float* __restrict__ x) {
    int i = blockIdx.x * blockDim.x + threadIdx.x;
    for (; i < 16777216; i += gridDim.x * blockDim.x) {
        float4 v = ((const float4*)x)[i];
        v.x = tf32r(v.x); v.y = tf32r(v.y); v.z = tf32r(v.z); v.w = tf32r(v.w);
        ((float4*)g_xr)[i] = v;
    }
}

// ---------------------------------------------------------------------------
// bias: g_bias[b][c] += sum_k x[b,254/255,k] * W[k][c]   (fp32 exact)
// ---------------------------------------------------------------------------
__global__ void __launch_bounds__(512) bias_kernel(
    const float* __restrict__ x,
    const float* __restrict__ pp,
    const float* __restrict__ pc) {
    __shared__ float xs[32 * 256];
    int b0 = blockIdx.x * 32;
    int ks = blockIdx.y;                 // 0..7
    int srow = (ks < 4) ? 254 : 255;
    int col0 = (ks & 3) * 256;
    const float* W = (ks < 4) ? pp : pc;
    int tid = threadIdx.x;
    for (int i = tid; i < 32 * 256; i += 512) {
        int bb = i >> 8, kk = i & 255;
        xs[i] = x[((size_t)(b0 + bb) * 256 + srow) * DD + col0 + kk];
    }
    __syncthreads();
    int c = tid;
    float acc[32];
#pragma unroll
    for (int bb = 0; bb < 32; bb++) acc[bb] = 0.0f;
    for (int kk = 0; kk < 256; kk++) {
        float w = W[(size_t)(col0 + kk) * PP + c];
#pragma unroll
        for (int bb = 0; bb < 32; bb++) acc[bb] += xs[(bb << 8) + kk] * w;
    }
#pragma unroll
    for (int bb = 0; bb < 32; bb++)
        atomicAdd(&g_bias[(size_t)(b0 + bb) * PP + c], acc[bb]);
}

// ---------------------------------------------------------------------------
// GEMM via mma.sync tf32.  CTA tile 128x256, 8 warps (2x4), warp tile 64x64.
// mode 0: A=g_xr (K=1024), +bias, tanh -> g_cA
// mode 1: A=g_cA (K=512), tanh -> g_cB
// mode 2: A=g_cB (K=512), tanh, dot scorer -> atomicAdd g_score
// ---------------------------------------------------------------------------
#define SAo   0
#define ABUF  18432      // 128 rows x 144B (36 floats)
#define SBo   36864
#define BBUF  33792      // 32 k x 1056B (264 floats)
#define SVEC  104448     // 256 floats
#define SM_TOTAL 105472

extern __shared__ char smg[];

__global__ void __launch_bounds__(256, 1)
gemm_kernel(const float* __restrict__ scorer, int mode) {
    uint32_t sa0 = smem_u32(smg);
    int tid = threadIdx.x;
    int lane = tid & 31, wid = tid >> 5;
    int warpM = wid & 1, warpN = wid >> 1;
    int gid = lane >> 2, tg = lane & 3;
    int tm = blockIdx.x, tn = blockIdx.y;
    int gr0 = tm * 128;

    const float* Abase;
    const float* Bbase;
    float* dstC = 0;
    int astr, nch;
    if (mode == 0) {
        Abase = g_xr + (size_t)gr0 * DD;  astr = DD;
        Bbase = g_wt + tn * 256;          nch = 32;  dstC = g_cA;
    } else if (mode == 1) {
        Abase = g_cA + (size_t)gr0 * PP;  astr = PP;
        Bbase = g_wt + 524288 + tn * 256; nch = 16;  dstC = g_cB;
    } else {
        Abase = g_cB + (size_t)gr0 * PP;  astr = PP;
        Bbase = g_wt + 786432 + tn * 256; nch = 16;
    }

    float* vec = (float*)(smg + SVEC);
    if (mode == 0) vec[tid] = g_bias[(size_t)(tm >> 1) * PP + tn * 256 + tid];
    if (mode == 2) vec[tid] = scorer[tn * 256 + tid];

    float acc[4][8][4];
#pragma unroll
    for (int mt = 0; mt < 4; mt++)
#pragma unroll
        for (int nt = 0; nt < 8; nt++)
#pragma unroll
            for (int q = 0; q < 4; q++) acc[mt][nt][q] = 0.0f;

    // ---- staging (cp.async, double-buffered) ----
    auto stage = [&](int j, int buf) {
        const float* As = Abase + j * 32;
#pragma unroll
        for (int t = 0; t < 4; t++) {
            int i = tid + t * 256;
            int r = i >> 3, sg = i & 7;
            cpa16(sa0 + SAo + buf * ABUF + r * 144 + sg * 16,
                  As + (size_t)r * astr + sg * 4);
        }
        const float* Bs = Bbase + (size_t)j * 32 * PP;
#pragma unroll
        for (int t = 0; t < 8; t++) {
            int i = tid + t * 256;
            int r = i >> 6, sg = i & 63;
            cpa16(sa0 + SBo + buf * BBUF + r * 1056 + sg * 16,
                  Bs + (size_t)r * PP + sg * 4);
        }
        asm volatile("cp.async.commit_group;" ::: "memory");
    };

    stage(0, 0);
    for (int j = 0; j < nch; j++) {
        if (j + 1 < nch) {
            stage(j + 1, (j + 1) & 1);
            asm volatile("cp.async.wait_group 1;" ::: "memory");
        } else {
            asm volatile("cp.async.wait_group 0;" ::: "memory");
        }
        __syncthreads();

        const float* As = (const float*)(smg + SAo + (j & 1) * ABUF);
        const float* Bs = (const float*)(smg + SBo + (j & 1) * BBUF);
        int mb = warpM * 64, nb = warpN * 64;

#pragma unroll
        for (int ks = 0; ks < 4; ks++) {
            int kb = ks * 8;
            uint32_t af[4][4];
#pragma unroll
            for (int mt = 0; mt < 4; mt++) {
                int r0 = mb + mt * 16 + gid;
                af[mt][0] = __float_as_uint(As[r0 * 36 + kb + tg]);
                af[mt][1] = __float_as_uint(As[(r0 + 8) * 36 + kb + tg]);
                af[mt][2] = __float_as_uint(As[r0 * 36 + kb + tg + 4]);
                af[mt][3] = __float_as_uint(As[(r0 + 8) * 36 + kb + tg + 4]);
            }
            uint32_t bf[8][2];
#pragma unroll
            for (int nt = 0; nt < 8; nt++) {
                int c0 = nb + nt * 8 + gid;
                bf[nt][0] = __float_as_uint(Bs[(kb + tg) * 264 + c0]);
                bf[nt][1] = __float_as_uint(Bs[(kb + tg + 4) * 264 + c0]);
            }
#pragma unroll
            for (int mt = 0; mt < 4; mt++)
#pragma unroll
                for (int nt = 0; nt < 8; nt++)
                    asm volatile(
                        "mma.sync.aligned.m16n8k8.row.col.f32.tf32.tf32.f32 "
                        "{%0,%1,%2,%3}, {%4,%5,%6,%7}, {%8,%9}, {%0,%1,%2,%3};"
                        : "+f"(acc[mt][nt][0]), "+f"(acc[mt][nt][1]),
                          "+f"(acc[mt][nt][2]), "+f"(acc[mt][nt][3])
                        : "r"(af[mt][0]), "r"(af[mt][1]),
                          "r"(af[mt][2]), "r"(af[mt][3]),
                          "r"(bf[nt][0]), "r"(bf[nt][1]));
        }
        __syncthreads();
    }

    // ---- epilogue ----
    if (mode < 2) {
#pragma unroll
        for (int mt = 0; mt < 4; mt++) {
            int rl = warpM * 64 + mt * 16 + gid;
            size_t rowa = (size_t)(gr0 + rl) * PP;
            size_t rowb = (size_t)(gr0 + rl + 8) * PP;
#pragma unroll
            for (int nt = 0; nt < 8; nt++) {
                int cl = warpN * 64 + nt * 8 + 2 * tg;
                int gc = tn * 256 + cl;
                float b0 = 0.f, b1 = 0.f;
                if (mode == 0) { b0 = vec[cl]; b1 = vec[cl + 1]; }
                float2 v0, v1;
                v0.x = tf32r(tanh_fast(acc[mt][nt][0] + b0));
                v0.y = tf32r(tanh_fast(acc[mt][nt][1] + b1));
                v1.x = tf32r(tanh_fast(acc[mt][nt][2] + b0));
                v1.y = tf32r(tanh_fast(acc[mt][nt][3] + b1));
                *(float2*)(dstC + rowa + gc) = v0;
                *(float2*)(dstC + rowb + gc) = v1;
            }
        }
    } else {
#pragma unroll
        for (int mt = 0; mt < 4; mt++) {
            float r0s = 0.f, r1s = 0.f;
#pragma unroll
            for (int nt = 0; nt < 8; nt++) {
                int cl = warpN * 64 + nt * 8 + 2 * tg;
                r0s += tanh_fast(acc[mt][nt][0]) * vec[cl]
                     + tanh_fast(acc[mt][nt][1]) * vec[cl + 1];
                r1s += tanh_fast(acc[mt][nt][2]) * vec[cl]
                     + tanh_fast(acc[mt][nt][3]) * vec[cl + 1];
            }
            r0s += __shfl_xor_sync(0xffffffffu, r0s, 1);
            r0s += __shfl_xor_sync(0xffffffffu, r0s, 2);
            r1s += __shfl_xor_sync(0xffffffffu, r1s, 1);
            r1s += __shfl_xor_sync(0xffffffffu, r1s, 2);
            if (tg == 0) {
                int rl = warpM * 64 + mt * 16 + gid;
                atomicAdd(&g_score[gr0 + rl], r0s);
                atomicAdd(&g_score[gr0 + rl + 8], r1s);
            }
        }
    }
}

// ---------------------------------------------------------------------------
// softmax: mask, exp, per-batch sum, normalize -> out[b][s]
// ---------------------------------------------------------------------------
__global__ void __launch_bounds__(256) softmax_kernel(
    float* __restrict__ out, const unsigned int* __restrict__ maskp) {
    __shared__ float red[8];
    int b = blockIdx.x, t = threadIdx.x;
    float e = 0.0f;
    if (t < SH) {
        unsigned int m = maskp[b * 256 + t];
        if (m != 0u) e = expf(g_score[b * 256 + t]);
    }
    float s = e;
    s += __shfl_xor_sync(0xffffffffu, s, 16);
    s += __shfl_xor_sync(0xffffffffu, s, 8);
    s += __shfl_xor_sync(0xffffffffu, s, 4);
    s += __shfl_xor_sync(0xffffffffu, s, 2);
    s += __shfl_xor_sync(0xffffffffu, s, 1);
    if ((t & 31) == 0) red[t >> 5] = s;
    __syncthreads();
    if (t == 0) {
        float tt = 0.f;
#pragma unroll
        for (int i = 0; i < 8; i++) tt += red[i];
        red[0] = tt + 1e-7f;
    }
    __syncthreads();
    if (t < SH) out[b * SH + t] = e / red[0];
}

// ---------------------------------------------------------------------------
extern "C" void kernel_launch(void* const* d_in, const int* in_sizes, int n_in,
                              void* d_out, int out_size) {
    const float* x      = (const float*)d_in[0];
    const float* phd    = (const float*)d_in[1];
    const float* pp     = (const float*)d_in[2];
    const float* pc     = (const float*)d_in[3];
    const float* hidden = (const float*)d_in[4];
    const float* scorer = (const float*)d_in[5];
    const unsigned int* mask = (const unsigned int*)d_in[6];
    float* out = (float*)d_out;

    cudaFuncSetAttribute(gemm_kernel,
                         cudaFuncAttributeMaxDynamicSharedMemorySize, SM_TOTAL);

    init_kernel<<<512, 256>>>();
    round_w_kernel<<<1024, 256>>>(phd, hidden);
    round_x_kernel<<<4096, 256>>>(x);
    bias_kernel<<<dim3(8, 8), 512>>>(x, pp, pc);

    dim3 grid(512, 2);
    gemm_kernel<<<grid, 256, SM_TOTAL>>>(scorer, 0);
    gemm_kernel<<<grid, 256, SM_TOTAL>>>(scorer, 1);
    gemm_kernel<<<grid, 256, SM_TOTAL>>>(scorer, 2);

    softmax_kernel<<<BB, 256>>>(out, mask);
}

// round 15
// speedup vs baseline: 3.9743x; 1.0010x over previous
#include <cuda_runtime.h>
#include <math.h>
#include <stdint.h>

// ---------------- problem constants ----------------
#define BB 256
#define DD 1024
#define PP 512
#define SH 254

// ---------------- device scratch (static; no runtime alloc) ----------------
__device__ float g_xr[67108864];     // x, tf32-rounded (256MB)
__device__ float g_wt[1048576];      // Wh | W1 | W2, [K][N], tf32-rounded
__device__ float g_cA[33554432];     // layer staging A (134MB)
__device__ float g_cB[33554432];     // layer staging B (134MB)
__device__ float g_bias[BB * PP];    // prep+child projection bias
__device__ float g_score[65536];     // raw scores (b*256 + s)

// ---------------- helpers ----------------
__device__ __forceinline__ uint32_t smem_u32(const void* p) {
    uint32_t a;
    asm("{ .reg .u64 t; cvta.to.shared.u64 t, %1; cvt.u32.u64 %0, t; }"
        : "=r"(a) : "l"(p));
    return a;
}
__device__ __forceinline__ float tf32r(float x) {   // round-to-nearest tf32
    uint32_t u;
    asm("cvt.rna.tf32.f32 %0, %1;" : "=r"(u) : "f"(x));
    return __uint_as_float(u);
}
__device__ __forceinline__ float tanh_fast(float x) {
    float y;
    asm("tanh.approx.f32 %0, %1;" : "=f"(y) : "f"(x));
    return y;
}
__device__ __forceinline__ void cpa16(uint32_t d, const void* s) {
    asm volatile("cp.async.cg.shared.global [%0], [%1], 16;" :: "r"(d), "l"(s));
}

// ---------------------------------------------------------------------------
// init: zero g_bias + g_score each replay
// ---------------------------------------------------------------------------
__global__ void init_kernel() {
    int i = blockIdx.x * blockDim.x + threadIdx.x;
    if (i < BB * PP) g_bias[i] = 0.0f;
    if (i < 65536)   g_score[i] = 0.0f;
}

// ---------------------------------------------------------------------------
// round weights into g_wt ([K][N] layout preserved), tf32 rna
// ---------------------------------------------------------------------------
__global__ void round_w_kernel(const float* __restrict__ ph,
                               const float* __restrict__ hidden) {
    int i = blockIdx.x * blockDim.x + threadIdx.x;
    for (; i < 1048576; i += gridDim.x * blockDim.x)
        g_wt[i] = tf32r(i < 524288 ? ph[i] : hidden[i - 524288]);
}

// ---------------------------------------------------------------------------
// round x into g_xr, tf32 rna (float4 grid-stride)
// ---------------------------------------------------------------------------
__global__ void round_x_kernel(const float* __restrict__ x) {
    int i = blockIdx.x * blockDim.x + threadIdx.x;
    for (; i < 16777216; i += gridDim.x * blockDim.x) {
        float4 v = ((const float4*)x)[i];
        v.x = tf32r(v.x); v.y = tf32r(v.y); v.z = tf32r(v.z); v.w = tf32r(v.w);
        ((float4*)g_xr)[i] = v;
    }
}

// ---------------------------------------------------------------------------
// bias: g_bias[b][c] += sum_k x[b,254/255,k] * W[k][c]   (fp32 exact)
// ---------------------------------------------------------------------------
__global__ void __launch_bounds__(512) bias_kernel(
    const float* __restrict__ x,
    const float* __restrict__ pp,
    const float* __restrict__ pc) {
    __shared__ float xs[32 * 256];
    int b0 = blockIdx.x * 32;
    int ks = blockIdx.y;                 // 0..7
    int srow = (ks < 4) ? 254 : 255;
    int col0 = (ks & 3) * 256;
    const float* W = (ks < 4) ? pp : pc;
    int tid = threadIdx.x;
    for (int i = tid; i < 32 * 256; i += 512) {
        int bb = i >> 8, kk = i & 255;
        xs[i] = x[((size_t)(b0 + bb) * 256 + srow) * DD + col0 + kk];
    }
    __syncthreads();
    int c = tid;
    float acc[32];
#pragma unroll
    for (int bb = 0; bb < 32; bb++) acc[bb] = 0.0f;
    for (int kk = 0; kk < 256; kk++) {
        float w = W[(size_t)(col0 + kk) * PP + c];
#pragma unroll
        for (int bb = 0; bb < 32; bb++) acc[bb] += xs[(bb << 8) + kk] * w;
    }
#pragma unroll
    for (int bb = 0; bb < 32; bb++)
        atomicAdd(&g_bias[(size_t)(b0 + bb) * PP + c], acc[bb]);
}

// ---------------------------------------------------------------------------
// GEMM via mma.sync tf32.  CTA tile 128x256, 8 warps (2x4), warp tile 64x64.
// mode 0: A=g_xr (K=1024), +bias, tanh -> g_cA
// mode 1: A=g_cA (K=512), tanh -> g_cB
// mode 2: A=g_cB (K=512), tanh, dot scorer -> atomicAdd g_score
// ---------------------------------------------------------------------------
#define SAo   0
#define ABUF  18432      // 128 rows x 144B (36 floats)
#define SBo   36864
#define BBUF  33792      // 32 k x 1056B (264 floats)
#define SVEC  104448     // 256 floats
#define SM_TOTAL 105472

extern __shared__ char smg[];

__global__ void __launch_bounds__(256, 1)
gemm_kernel(const float* __restrict__ scorer, int mode) {
    uint32_t sa0 = smem_u32(smg);
    int tid = threadIdx.x;
    int lane = tid & 31, wid = tid >> 5;
    int warpM = wid & 1, warpN = wid >> 1;
    int gid = lane >> 2, tg = lane & 3;
    int tm = blockIdx.x, tn = blockIdx.y;
    int gr0 = tm * 128;

    const float* Abase;
    const float* Bbase;
    float* dstC = 0;
    int astr, nch;
    if (mode == 0) {
        Abase = g_xr + (size_t)gr0 * DD;  astr = DD;
        Bbase = g_wt + tn * 256;          nch = 32;  dstC = g_cA;
    } else if (mode == 1) {
        Abase = g_cA + (size_t)gr0 * PP;  astr = PP;
        Bbase = g_wt + 524288 + tn * 256; nch = 16;  dstC = g_cB;
    } else {
        Abase = g_cB + (size_t)gr0 * PP;  astr = PP;
        Bbase = g_wt + 786432 + tn * 256; nch = 16;
    }

    float* vec = (float*)(smg + SVEC);
    if (mode == 0) vec[tid] = g_bias[(size_t)(tm >> 1) * PP + tn * 256 + tid];
    if (mode == 2) vec[tid] = scorer[tn * 256 + tid];

    float acc[4][8][4];
#pragma unroll
    for (int mt = 0; mt < 4; mt++)
#pragma unroll
        for (int nt = 0; nt < 8; nt++)
#pragma unroll
            for (int q = 0; q < 4; q++) acc[mt][nt][q] = 0.0f;

    // ---- staging (cp.async, double-buffered) ----
    auto stage = [&](int j, int buf) {
        const float* As = Abase + j * 32;
#pragma unroll
        for (int t = 0; t < 4; t++) {
            int i = tid + t * 256;
            int r = i >> 3, sg = i & 7;
            cpa16(sa0 + SAo + buf * ABUF + r * 144 + sg * 16,
                  As + (size_t)r * astr + sg * 4);
        }
        const float* Bs = Bbase + (size_t)j * 32 * PP;
#pragma unroll
        for (int t = 0; t < 8; t++) {
            int i = tid + t * 256;
            int r = i >> 6, sg = i & 63;
            cpa16(sa0 + SBo + buf * BBUF + r * 1056 + sg * 16,
                  Bs + (size_t)r * PP + sg * 4);
        }
        asm volatile("cp.async.commit_group;" ::: "memory");
    };

    stage(0, 0);
    for (int j = 0; j < nch; j++) {
        if (j + 1 < nch) {
            stage(j + 1, (j + 1) & 1);
            asm volatile("cp.async.wait_group 1;" ::: "memory");
        } else {
            asm volatile("cp.async.wait_group 0;" ::: "memory");
        }
        __syncthreads();

        const float* As = (const float*)(smg + SAo + (j & 1) * ABUF);
        const float* Bs = (const float*)(smg + SBo + (j & 1) * BBUF);
        int mb = warpM * 64, nb = warpN * 64;

#pragma unroll
        for (int ks = 0; ks < 4; ks++) {
            int kb = ks * 8;
            uint32_t af[4][4];
#pragma unroll
            for (int mt = 0; mt < 4; mt++) {
                int r0 = mb + mt * 16 + gid;
                af[mt][0] = __float_as_uint(As[r0 * 36 + kb + tg]);
                af[mt][1] = __float_as_uint(As[(r0 + 8) * 36 + kb + tg]);
                af[mt][2] = __float_as_uint(As[r0 * 36 + kb + tg + 4]);
                af[mt][3] = __float_as_uint(As[(r0 + 8) * 36 + kb + tg + 4]);
            }
            uint32_t bf[8][2];
#pragma unroll
            for (int nt = 0; nt < 8; nt++) {
                int c0 = nb + nt * 8 + gid;
                bf[nt][0] = __float_as_uint(Bs[(kb + tg) * 264 + c0]);
                bf[nt][1] = __float_as_uint(Bs[(kb + tg + 4) * 264 + c0]);
            }
#pragma unroll
            for (int mt = 0; mt < 4; mt++)
#pragma unroll
                for (int nt = 0; nt < 8; nt++)
                    asm volatile(
                        "mma.sync.aligned.m16n8k8.row.col.f32.tf32.tf32.f32 "
                        "{%0,%1,%2,%3}, {%4,%5,%6,%7}, {%8,%9}, {%0,%1,%2,%3};"
                        : "+f"(acc[mt][nt][0]), "+f"(acc[mt][nt][1]),
                          "+f"(acc[mt][nt][2]), "+f"(acc[mt][nt][3])
                        : "r"(af[mt][0]), "r"(af[mt][1]),
                          "r"(af[mt][2]), "r"(af[mt][3]),
                          "r"(bf[nt][0]), "r"(bf[nt][1]));
        }
        __syncthreads();
    }

    // ---- epilogue ----
    if (mode < 2) {
#pragma unroll
        for (int mt = 0; mt < 4; mt++) {
            int rl = warpM * 64 + mt * 16 + gid;
            size_t rowa = (size_t)(gr0 + rl) * PP;
            size_t rowb = (size_t)(gr0 + rl + 8) * PP;
#pragma unroll
            for (int nt = 0; nt < 8; nt++) {
                int cl = warpN * 64 + nt * 8 + 2 * tg;
                int gc = tn * 256 + cl;
                float b0 = 0.f, b1 = 0.f;
                if (mode == 0) { b0 = vec[cl]; b1 = vec[cl + 1]; }
                float2 v0, v1;
                v0.x = tf32r(tanh_fast(acc[mt][nt][0] + b0));
                v0.y = tf32r(tanh_fast(acc[mt][nt][1] + b1));
                v1.x = tf32r(tanh_fast(acc[mt][nt][2] + b0));
                v1.y = tf32r(tanh_fast(acc[mt][nt][3] + b1));
                *(float2*)(dstC + rowa + gc) = v0;
                *(float2*)(dstC + rowb + gc) = v1;
            }
        }
    } else {
#pragma unroll
        for (int mt = 0; mt < 4; mt++) {
            float r0s = 0.f, r1s = 0.f;
#pragma unroll
            for (int nt = 0; nt < 8; nt++) {
                int cl = warpN * 64 + nt * 8 + 2 * tg;
                r0s += tanh_fast(acc[mt][nt][0]) * vec[cl]
                     + tanh_fast(acc[mt][nt][1]) * vec[cl + 1];
                r1s += tanh_fast(acc[mt][nt][2]) * vec[cl]
                     + tanh_fast(acc[mt][nt][3]) * vec[cl + 1];
            }
            r0s += __shfl_xor_sync(0xffffffffu, r0s, 1);
            r0s += __shfl_xor_sync(0xffffffffu, r0s, 2);
            r1s += __shfl_xor_sync(0xffffffffu, r1s, 1);
            r1s += __shfl_xor_sync(0xffffffffu, r1s, 2);
            if (tg == 0) {
                int rl = warpM * 64 + mt * 16 + gid;
                atomicAdd(&g_score[gr0 + rl], r0s);
                atomicAdd(&g_score[gr0 + rl + 8], r1s);
            }
        }
    }
}

// ---------------------------------------------------------------------------
// softmax: mask, exp, per-batch sum, normalize -> out[b][s]
// ---------------------------------------------------------------------------
__global__ void __launch_bounds__(256) softmax_kernel(
    float* __restrict__ out, const unsigned int* __restrict__ maskp) {
    __shared__ float red[8];
    int b = blockIdx.x, t = threadIdx.x;
    float e = 0.0f;
    if (t < SH) {
        unsigned int m = maskp[b * 256 + t];
        if (m != 0u) e = expf(g_score[b * 256 + t]);
    }
    float s = e;
    s += __shfl_xor_sync(0xffffffffu, s, 16);
    s += __shfl_xor_sync(0xffffffffu, s, 8);
    s += __shfl_xor_sync(0xffffffffu, s, 4);
    s += __shfl_xor_sync(0xffffffffu, s, 2);
    s += __shfl_xor_sync(0xffffffffu, s, 1);
    if ((t & 31) == 0) red[t >> 5] = s;
    __syncthreads();
    if (t == 0) {
        float tt = 0.f;
#pragma unroll
        for (int i = 0; i < 8; i++) tt += red[i];
        red[0] = tt + 1e-7f;
    }
    __syncthreads();
    if (t < SH) out[b * SH + t] = e / red[0];
}

// ---------------------------------------------------------------------------
extern "C" void kernel_launch(void* const* d_in, const int* in_sizes, int n_in,
                              void* d_out, int out_size) {
    const float* x      = (const float*)d_in[0];
    const float* phd    = (const float*)d_in[1];
    const float* pp     = (const float*)d_in[2];
    const float* pc     = (const float*)d_in[3];
    const float* hidden = (const float*)d_in[4];
    const float* scorer = (const float*)d_in[5];
    const unsigned int* mask = (const unsigned int*)d_in[6];
    float* out = (float*)d_out;

    cudaFuncSetAttribute(gemm_kernel,
                         cudaFuncAttributeMaxDynamicSharedMemorySize, SM_TOTAL);

    init_kernel<<<512, 256>>>();
    round_w_kernel<<<1024, 256>>>(phd, hidden);
    round_x_kernel<<<4096, 256>>>(x);
    bias_kernel<<<dim3(8, 8), 512>>>(x, pp, pc);

    dim3 grid(512, 2);
    gemm_kernel<<<grid, 256, SM_TOTAL>>>(scorer, 0);
    gemm_kernel<<<grid, 256, SM_TOTAL>>>(scorer, 1);
    gemm_kernel<<<grid, 256, SM_TOTAL>>>(scorer, 2);

    softmax_kernel<<<BB, 256>>>(out, mask);
}